// round 16
// baseline (speedup 1.0000x reference)
#include <cuda_runtime.h>
#include <cuda_bf16.h>
#include <cuda_fp16.h>
#include <stdint.h>
#include <math.h>

#define BATCH  4
#define SEQ    2048
#define INDIM  1024
#define DMODEL 1024
#define NHEADS 16
#define HDIM   64
#define KTOT   1024

// Q prescale: 1/sqrt(64) * log2(e)  (softmax runs in base-2)
#define QSCALE_LOG2E 0.1803368801111244f

// ---------------------------------------------------------------------------
// Device scratch (all plain fp16)
// ---------------------------------------------------------------------------
#define QKV_ELE (BATCH*NHEADS*SEQ*HDIM)
__device__ __half g_Q16[QKV_ELE];                        // plain fp16, pre-scaled
__device__ __half g_K16[QKV_ELE];                        // plain fp16
__device__ __half g_V16[QKV_ELE];                        // plain fp16
__device__ __half g_AO16[BATCH*SEQ*DMODEL];              // plain fp16
__device__ __half g_x16[BATCH*SEQ*INDIM];                // plain fp16
__device__ __half g_W16[4][DMODEL*INDIM];                // plain fp16

// ---------------------------------------------------------------------------
// PTX helpers
// ---------------------------------------------------------------------------
__device__ __forceinline__ uint32_t smem_u32(const void* p) {
    uint32_t a;
    asm("{ .reg .u64 t; cvta.to.shared.u64 t, %1; cvt.u32.u64 %0, t; }"
        : "=r"(a) : "l"(p));
    return a;
}
__device__ __forceinline__ void cp_async16(uint32_t dst, const void* src) {
    asm volatile("cp.async.cg.shared.global [%0], [%1], 16;" :: "r"(dst), "l"(src));
}
__device__ __forceinline__ void cp_commit()  { asm volatile("cp.async.commit_group;"); }
__device__ __forceinline__ void cp_wait0()   { asm volatile("cp.async.wait_group 0;"); }
__device__ __forceinline__ void cp_wait1()   { asm volatile("cp.async.wait_group 1;"); }

__device__ __forceinline__ void ldsm_x4(uint32_t* r, uint32_t a) {
    asm volatile("ldmatrix.sync.aligned.m8n8.x4.shared.b16 {%0,%1,%2,%3}, [%4];"
        : "=r"(r[0]), "=r"(r[1]), "=r"(r[2]), "=r"(r[3]) : "r"(a));
}
__device__ __forceinline__ void ldsm_x4_t(uint32_t* r, uint32_t a) {
    asm volatile("ldmatrix.sync.aligned.m8n8.x4.trans.shared.b16 {%0,%1,%2,%3}, [%4];"
        : "=r"(r[0]), "=r"(r[1]), "=r"(r[2]), "=r"(r[3]) : "r"(a));
}
__device__ __forceinline__ void mma_f16(float* c, const uint32_t* a, const uint32_t* b) {
    asm volatile(
        "mma.sync.aligned.m16n8k16.row.col.f32.f16.f16.f32 "
        "{%0,%1,%2,%3}, {%4,%5,%6,%7}, {%8,%9}, {%0,%1,%2,%3};"
        : "+f"(c[0]), "+f"(c[1]), "+f"(c[2]), "+f"(c[3])
        : "r"(a[0]), "r"(a[1]), "r"(a[2]), "r"(a[3]), "r"(b[0]), "r"(b[1]));
}

__device__ __forceinline__ uint32_t pack_h16(float x, float y) {
    return ((uint32_t)__half_as_ushort(__float2half(y)) << 16)
         | __half_as_ushort(__float2half(x));
}

// ---------------------------------------------------------------------------
// fused converter: grid.y 0..7 -> x chunks, 8..11 -> Wq/Wk/Wv/Wo
// each (block, y) handles 1024*1024 elems? no: 1024 blocks x 1024 elems
// ---------------------------------------------------------------------------
__global__ __launch_bounds__(256) void conv_all(
    const float* __restrict__ x,
    const float* __restrict__ Wq, const float* __restrict__ Wk,
    const float* __restrict__ Wv, const float* __restrict__ Wo)
{
    const int seg = blockIdx.y;
    const float* src;
    __half* dst;
    if (seg < 8) {                         // x: 8 chunks of 1M elems
        src = x   + (size_t)seg * (1024*1024);
        dst = g_x16 + (size_t)seg * (1024*1024);
    } else {
        const int w = seg - 8;
        src = (w == 0) ? Wq : (w == 1) ? Wk : (w == 2) ? Wv : Wo;
        dst = g_W16[w];
    }
    size_t i = ((size_t)blockIdx.x * 256 + threadIdx.x) * 4;
    float4 v = *(const float4*)(src + i);
    __half o[4] = { __float2half(v.x), __float2half(v.y),
                    __float2half(v.z), __float2half(v.w) };
    *(uint2*)(dst + i) = *(uint2*)o;
}

// ---------------------------------------------------------------------------
// fp16 1-MMA GEMM:  C[m,n] = sum_k A[m,k]*W[n,k] + bias[n]
// 128x128 block, 8 warps, BK=64, 3-stage cp.async (wait_group 1), 2 CTAs/SM.
// mode 0: QKV -> Q (scaled) / K / V plain fp16, scatter [B,H,S,Dh]
// mode 1: O-proj -> fp32 out
// ---------------------------------------------------------------------------
#define BM 128
#define BN 128
#define BK 64
#define NCH (KTOT/BK)          // 16
#define LDK 72
#define TILE_E (128*LDK)       // 9216
#define STAGE_E (2*TILE_E)
#define NSTAGE 3
#define GEMM_SMEM_BYTES (NSTAGE*STAGE_E*2)   // 110592

struct GemmArgs {
    const float* bias0; const float* bias1; const float* bias2;
    float* out_o;
    int mode;
};

__global__ __launch_bounds__(256, 2) void hl_gemm(GemmArgs args)
{
    extern __shared__ __align__(16) char dsm[];
    __half* smT = (__half*)dsm;

    const int t    = threadIdx.x;
    const int wid  = t >> 5;
    const int lane = t & 31;
    const int z    = blockIdx.z;
    const int m0   = blockIdx.y * BM;
    const int n0   = blockIdx.x * BN;
    const int wm   = wid & 1;
    const int wn   = wid >> 1;

    const __half *Ax, *Bx;
    const float* bias;
    if (args.mode == 0) {
        Ax = g_x16;
        Bx = g_W16[z];
        bias = (z == 0) ? args.bias0 : (z == 1) ? args.bias1 : args.bias2;
    } else {
        Ax = g_AO16;
        Bx = g_W16[3];
        bias = args.bias0;
    }
    const __half* srcs[2] = { Ax, Bx };
    const int r0s[2] = { m0, n0 };

    const uint32_t ub = smem_u32(smT);
    const uint32_t abase = (uint32_t)(((wm*64 + (lane & 15)) * LDK + ((lane >> 4) << 3)) * 2);
    const uint32_t bbase = (uint32_t)(((wn*32 + ((lane >> 4) << 3) + (lane & 7)) * LDK
                                      + (((lane >> 3) & 1) << 3)) * 2);

    float c[4][4][4];
#pragma unroll
    for (int mi = 0; mi < 4; mi++)
#pragma unroll
        for (int nj = 0; nj < 4; nj++)
#pragma unroll
            for (int r = 0; r < 4; r++) c[mi][nj][r] = 0.f;

    auto load_stage = [&](int stage, int kc) {
#pragma unroll
        for (int it = 0; it < 8; it++) {
            int idx  = t + it * 256;
            int tile = idx >> 10;
            int rem  = idx & 1023;
            int row  = rem >> 3;
            int ch   = rem & 7;
            const __half* sp = srcs[tile]
                + (size_t)(r0s[tile] + row) * KTOT + kc * BK + ch * 8;
            uint32_t dp = ub + (uint32_t)((stage * 2 + tile) * TILE_E + row * LDK + ch * 8) * 2;
            cp_async16(dp, sp);
        }
        cp_commit();
    };

    load_stage(0, 0);
    load_stage(1, 1);

    for (int kc = 0; kc < NCH; kc++) {
        if (kc + 1 < NCH) cp_wait1(); else cp_wait0();
        __syncthreads();
        if (kc + 2 < NCH) load_stage((kc + 2) % NSTAGE, kc + 2);

        const int s = kc % NSTAGE;
        const uint32_t uA = ub + (uint32_t)((s*2 + 0) * TILE_E) * 2;
        const uint32_t uB = ub + (uint32_t)((s*2 + 1) * TILE_E) * 2;

#pragma unroll
        for (int ks = 0; ks < 4; ks++) {
            uint32_t a[4][4];
#pragma unroll
            for (int mi = 0; mi < 4; mi++)
                ldsm_x4(a[mi], uA + abase + (uint32_t)(mi * 16 * LDK * 2) + ks * 32);
            uint32_t b[2][4];
#pragma unroll
            for (int j2 = 0; j2 < 2; j2++)
                ldsm_x4(b[j2], uB + bbase + (uint32_t)(j2 * 16 * LDK * 2) + ks * 32);
#pragma unroll
            for (int mi = 0; mi < 4; mi++)
#pragma unroll
                for (int nj = 0; nj < 4; nj++)
                    mma_f16(c[mi][nj], a[mi], &b[nj >> 1][(nj & 1) * 2]);
        }
    }

    // -------- register epilogue --------
    const float qscale = (args.mode == 0 && z == 0) ? QSCALE_LOG2E : 1.0f;
    float2 bv[4];
    int nn[4];
#pragma unroll
    for (int nj = 0; nj < 4; nj++) {
        nn[nj] = n0 + wn*32 + nj*8 + (lane & 3)*2;
        bv[nj] = *(const float2*)&bias[nn[nj]];
    }

    if (args.mode == 0) {
        __half* dst = (z == 0) ? g_Q16 : (z == 1) ? g_K16 : g_V16;
#pragma unroll
        for (int mi = 0; mi < 4; mi++) {
#pragma unroll
            for (int half = 0; half < 2; half++) {
                const int m  = m0 + wm*64 + mi*16 + (lane >> 2) + half*8;
                const int bb = m >> 11;
                const int ss = m & (SEQ - 1);
#pragma unroll
                for (int nj = 0; nj < 4; nj++) {
                    const int n  = nn[nj];
                    const int h  = n >> 6;
                    const int dh = n & 63;
                    const float v0 = (c[mi][nj][half*2+0] + bv[nj].x) * qscale;
                    const float v1 = (c[mi][nj][half*2+1] + bv[nj].y) * qscale;
                    const size_t off = (((size_t)bb * NHEADS + h) * SEQ + ss) * HDIM + dh;
                    *(uint32_t*)(dst + off) = pack_h16(v0, v1);
                }
            }
        }
    } else {
        float* outp = args.out_o;
#pragma unroll
        for (int mi = 0; mi < 4; mi++) {
#pragma unroll
            for (int half = 0; half < 2; half++) {
                const int m = m0 + wm*64 + mi*16 + (lane >> 2) + half*8;
#pragma unroll
                for (int nj = 0; nj < 4; nj++) {
                    const float v0 = c[mi][nj][half*2+0] + bv[nj].x;
                    const float v1 = c[mi][nj][half*2+1] + bv[nj].y;
                    *(float2*)(outp + (size_t)m * DMODEL + nn[nj]) = make_float2(v0, v1);
                }
            }
        }
    }
}

// ---------------------------------------------------------------------------
// Register-resident causal flash attention — all plain fp16 (unchanged R15).
// ---------------------------------------------------------------------------
#define ASTR 72
#define KVBUF 18432
#define ATTN_SMEM_BYTES (18432 + 2*KVBUF)   // 55296

__global__ __launch_bounds__(256, 2) void attn_tc()
{
    extern __shared__ __align__(16) char asmem[];
    __half* sQ = (__half*)(asmem);

    const int t    = threadIdx.x;
    const int wid  = t >> 5;
    const int lane = t & 31;
    const int bq   = gridDim.x - 1 - blockIdx.x;   // heavy tiles first
    const int h    = blockIdx.y;
    const int bb   = blockIdx.z;
    const int q0   = bq * 128;
    const size_t base = ((size_t)bb * NHEADS + h) * SEQ * HDIM;

    const char* gsrc[2] = { (const char*)g_K16, (const char*)g_V16 };

    auto load_kv = [&](int buf, int k0) {
        char* dst0 = asmem + 18432 + buf * KVBUF;
#pragma unroll
        for (int it = 0; it < 4; it++) {
            int idx = t + it * 256;
            int a   = idx >> 9;
            int rem = idx & 511;
            int row = rem >> 3, ch = rem & 7;
            uint32_t dp = smem_u32(dst0 + a * 9216 + (row * ASTR + ch * 8) * 2);
            cp_async16(dp, gsrc[a] + (base + (size_t)(k0 + row) * HDIM + ch * 8) * 2);
        }
        cp_commit();
    };

    {
#pragma unroll
        for (int it = 0; it < 4; it++) {
            int idx = t + it * 256;
            int row = idx >> 3, ch = idx & 7;
            uint32_t dp = smem_u32(asmem + (row * ASTR + ch * 8) * 2);
            cp_async16(dp, g_Q16 + base + (size_t)(q0 + row) * HDIM + ch * 8);
        }
        cp_commit();
    }
    load_kv(0, 0);

    const uint32_t uQ = smem_u32(sQ);
    const uint32_t aoff  = (uint32_t)(((wid*16 + (lane & 15)) * ASTR + ((lane >> 4) << 3)) * 2);
    const uint32_t kboff = (uint32_t)(((((lane >> 4) << 3) + (lane & 7)) * ASTR + (((lane >> 3) & 1) << 3)) * 2);
    const uint32_t vboff = (uint32_t)((((((lane >> 3) & 1) << 3) + (lane & 7)) * ASTR + ((lane >> 4) << 3)) * 2);

    float o[8][4];
#pragma unroll
    for (int j = 0; j < 8; j++)
#pragma unroll
        for (int r = 0; r < 4; r++) o[j][r] = 0.f;

    const int rA = q0 + wid*16 + (lane >> 2);
    const int rB = rA + 8;
    const int qwmin = q0 + wid*16;
    const int qwmax = qwmin + 15;
    float mA = -1e30f, mB = -1e30f, lA = 0.f, lB = 0.f;

    const int nkt = 2*bq + 2;
    for (int kt = 0; kt < nkt; kt++) {
        const int k0 = kt * 64;
        cp_wait0();
        __syncthreads();
        if (kt + 1 < nkt) load_kv((kt + 1) & 1, k0 + 64);

        const uint32_t ukv = smem_u32(asmem + 18432 + (kt & 1) * KVBUF);
        const uint32_t uK = ukv, uV = ukv + 9216;

        if (k0 <= qwmax) {
            float c[8][4];
#pragma unroll
            for (int j = 0; j < 8; j++)
#pragma unroll
                for (int r = 0; r < 4; r++) c[j][r] = 0.f;

#pragma unroll
            for (int ks = 0; ks < 4; ks++) {
                uint32_t a[4];
                ldsm_x4(a, uQ + aoff + ks*32);
#pragma unroll
                for (int jp = 0; jp < 4; jp++) {
                    if (k0 + jp*16 <= qwmax) {
                        uint32_t bk[4];
                        ldsm_x4(bk, uK + kboff + (uint32_t)(jp*16*ASTR*2) + ks*32);
                        mma_f16(c[2*jp],   a, bk);
                        mma_f16(c[2*jp+1], a, bk+2);
                    }
                }
            }

            if (k0 + 63 > qwmin) {
#pragma unroll
                for (int j = 0; j < 8; j++) {
                    int colb = k0 + j*8 + (lane & 3)*2;
                    if (colb     > rA) c[j][0] = -1e30f;
                    if (colb + 1 > rA) c[j][1] = -1e30f;
                    if (colb     > rB) c[j][2] = -1e30f;
                    if (colb + 1 > rB) c[j][3] = -1e30f;
                }
            }

            float vmA = -1e30f, vmB = -1e30f;
#pragma unroll
            for (int j = 0; j < 8; j++) {
                vmA = fmaxf(vmA, fmaxf(c[j][0], c[j][1]));
                vmB = fmaxf(vmB, fmaxf(c[j][2], c[j][3]));
            }
            vmA = fmaxf(vmA, __shfl_xor_sync(0xffffffffu, vmA, 1));
            vmA = fmaxf(vmA, __shfl_xor_sync(0xffffffffu, vmA, 2));
            vmB = fmaxf(vmB, __shfl_xor_sync(0xffffffffu, vmB, 1));
            vmB = fmaxf(vmB, __shfl_xor_sync(0xffffffffu, vmB, 2));
            const float mnA = fmaxf(mA, vmA);
            const float mnB = fmaxf(mB, vmB);

            float sA = 0.f, sB = 0.f;
#pragma unroll
            for (int j = 0; j < 8; j++) {
                c[j][0] = exp2f(c[j][0] - mnA);
                c[j][1] = exp2f(c[j][1] - mnA);
                c[j][2] = exp2f(c[j][2] - mnB);
                c[j][3] = exp2f(c[j][3] - mnB);
                sA += c[j][0] + c[j][1];
                sB += c[j][2] + c[j][3];
            }
            sA += __shfl_xor_sync(0xffffffffu, sA, 1);
            sA += __shfl_xor_sync(0xffffffffu, sA, 2);
            sB += __shfl_xor_sync(0xffffffffu, sB, 1);
            sB += __shfl_xor_sync(0xffffffffu, sB, 2);

            const float soA = exp2f(mA - mnA);
            const float soB = exp2f(mB - mnB);
            lA = lA * soA + sA;  mA = mnA;
            lB = lB * soB + sB;  mB = mnB;

#pragma unroll
            for (int j = 0; j < 8; j++) {
                o[j][0] *= soA; o[j][1] *= soA;
                o[j][2] *= soB; o[j][3] *= soB;
            }

#pragma unroll
            for (int kk = 0; kk < 4; kk++) {
                if (k0 + kk*16 <= qwmax) {
                    uint32_t p[4];
                    p[0] = pack_h16(c[2*kk][0],   c[2*kk][1]);
                    p[1] = pack_h16(c[2*kk][2],   c[2*kk][3]);
                    p[2] = pack_h16(c[2*kk+1][0], c[2*kk+1][1]);
                    p[3] = pack_h16(c[2*kk+1][2], c[2*kk+1][3]);
#pragma unroll
                    for (int jp = 0; jp < 4; jp++) {
                        uint32_t v[4];
                        ldsm_x4_t(v, uV + vboff + (uint32_t)(kk*16*ASTR*2) + jp*32);
                        mma_f16(o[2*jp],   p, v);
                        mma_f16(o[2*jp+1], p, v+2);
                    }
                }
            }
        }
    }

    {
        const float invA = 1.f / lA;
        const float invB = 1.f / lB;
        const size_t offA = ((size_t)bb * SEQ + rA) * DMODEL + h * HDIM + (lane & 3) * 2;
        const size_t offB = ((size_t)bb * SEQ + rB) * DMODEL + h * HDIM + (lane & 3) * 2;
#pragma unroll
        for (int j = 0; j < 8; j++) {
            *(uint32_t*)(g_AO16 + offA + j*8) = pack_h16(o[j][0] * invA, o[j][1] * invA);
            *(uint32_t*)(g_AO16 + offB + j*8) = pack_h16(o[j][2] * invB, o[j][3] * invB);
        }
    }
}

// ---------------------------------------------------------------------------
extern "C" void kernel_launch(void* const* d_in, const int* in_sizes, int n_in,
                              void* d_out, int out_size)
{
    const float* x  = (const float*)d_in[0];
    const float* Wq = (const float*)d_in[1];
    const float* bq = (const float*)d_in[2];
    const float* Wk = (const float*)d_in[3];
    const float* bk = (const float*)d_in[4];
    const float* Wv = (const float*)d_in[5];
    const float* bv = (const float*)d_in[6];
    const float* Wo = (const float*)d_in[7];
    const float* bo = (const float*)d_in[8];
    float* out = (float*)d_out;

    cudaFuncSetAttribute(hl_gemm, cudaFuncAttributeMaxDynamicSharedMemorySize, GEMM_SMEM_BYTES);
    cudaFuncSetAttribute(attn_tc, cudaFuncAttributeMaxDynamicSharedMemorySize, ATTN_SMEM_BYTES);

    // 12 segments x 1024 blocks x 1024 elems: 8 chunks of x (8.4M) + 4 W (1M each)
    conv_all<<<dim3(1024, 12), 256>>>(x, Wq, Wk, Wv, Wo);

    GemmArgs qa;
    qa.bias0 = bq; qa.bias1 = bk; qa.bias2 = bv; qa.out_o = nullptr; qa.mode = 0;
    hl_gemm<<<dim3(DMODEL/BN, (BATCH*SEQ)/BM, 3), 256, GEMM_SMEM_BYTES>>>(qa);

    attn_tc<<<dim3(SEQ/128, NHEADS, BATCH), 256, ATTN_SMEM_BYTES>>>();

    GemmArgs oa;
    oa.bias0 = bo; oa.bias1 = nullptr; oa.bias2 = nullptr; oa.out_o = out; oa.mode = 1;
    hl_gemm<<<dim3(DMODEL/BN, (BATCH*SEQ)/BM, 1), 256, GEMM_SMEM_BYTES>>>(oa);
}

// round 17
// speedup vs baseline: 1.0567x; 1.0567x over previous
#include <cuda_runtime.h>
#include <cuda_bf16.h>
#include <cuda_fp16.h>
#include <stdint.h>
#include <math.h>

#define BATCH  4
#define SEQ    2048
#define INDIM  1024
#define DMODEL 1024
#define NHEADS 16
#define HDIM   64
#define KTOT   1024

// Q prescale: 1/sqrt(64) * log2(e)  (softmax runs in base-2)
#define QSCALE_LOG2E 0.1803368801111244f

// ---------------------------------------------------------------------------
// Device scratch (all plain fp16)
// ---------------------------------------------------------------------------
#define QKV_ELE (BATCH*NHEADS*SEQ*HDIM)
__device__ __half g_Q16[QKV_ELE];                        // plain fp16, pre-scaled
__device__ __half g_K16[QKV_ELE];                        // plain fp16
__device__ __half g_V16[QKV_ELE];                        // plain fp16
__device__ __half g_AO16[BATCH*SEQ*DMODEL];              // plain fp16
__device__ __half g_x16[BATCH*SEQ*INDIM];                // plain fp16
__device__ __half g_W16[4][DMODEL*INDIM];                // plain fp16

// ---------------------------------------------------------------------------
// PTX helpers
// ---------------------------------------------------------------------------
__device__ __forceinline__ uint32_t smem_u32(const void* p) {
    uint32_t a;
    asm("{ .reg .u64 t; cvta.to.shared.u64 t, %1; cvt.u32.u64 %0, t; }"
        : "=r"(a) : "l"(p));
    return a;
}
__device__ __forceinline__ void cp_async16(uint32_t dst, const void* src) {
    asm volatile("cp.async.cg.shared.global [%0], [%1], 16;" :: "r"(dst), "l"(src));
}
__device__ __forceinline__ void cp_commit()  { asm volatile("cp.async.commit_group;"); }
__device__ __forceinline__ void cp_wait0()   { asm volatile("cp.async.wait_group 0;"); }
__device__ __forceinline__ void cp_wait1()   { asm volatile("cp.async.wait_group 1;"); }

__device__ __forceinline__ void ldsm_x4(uint32_t* r, uint32_t a) {
    asm volatile("ldmatrix.sync.aligned.m8n8.x4.shared.b16 {%0,%1,%2,%3}, [%4];"
        : "=r"(r[0]), "=r"(r[1]), "=r"(r[2]), "=r"(r[3]) : "r"(a));
}
__device__ __forceinline__ void ldsm_x4_t(uint32_t* r, uint32_t a) {
    asm volatile("ldmatrix.sync.aligned.m8n8.x4.trans.shared.b16 {%0,%1,%2,%3}, [%4];"
        : "=r"(r[0]), "=r"(r[1]), "=r"(r[2]), "=r"(r[3]) : "r"(a));
}
__device__ __forceinline__ void mma_f16(float* c, const uint32_t* a, const uint32_t* b) {
    asm volatile(
        "mma.sync.aligned.m16n8k16.row.col.f32.f16.f16.f32 "
        "{%0,%1,%2,%3}, {%4,%5,%6,%7}, {%8,%9}, {%0,%1,%2,%3};"
        : "+f"(c[0]), "+f"(c[1]), "+f"(c[2]), "+f"(c[3])
        : "r"(a[0]), "r"(a[1]), "r"(a[2]), "r"(a[3]), "r"(b[0]), "r"(b[1]));
}

// single-instruction base-2 exp (MUFU.EX2), independent of nvcc fast-math flags
__device__ __forceinline__ float ex2_fast(float x) {
    float r;
    asm("ex2.approx.ftz.f32 %0, %1;" : "=f"(r) : "f"(x));
    return r;
}
// single-instruction fp32x2 -> fp16x2 pack: low = x, high = y
__device__ __forceinline__ uint32_t pack_h16(float x, float y) {
    uint32_t r;
    asm("cvt.rn.f16x2.f32 %0, %1, %2;" : "=r"(r) : "f"(y), "f"(x));
    return r;
}

// ---------------------------------------------------------------------------
// fused converter: grid.y 0..7 -> x chunks, 8..11 -> Wq/Wk/Wv/Wo
// ---------------------------------------------------------------------------
__global__ __launch_bounds__(256) void conv_all(
    const float* __restrict__ x,
    const float* __restrict__ Wq, const float* __restrict__ Wk,
    const float* __restrict__ Wv, const float* __restrict__ Wo)
{
    const int seg = blockIdx.y;
    const float* src;
    __half* dst;
    if (seg < 8) {                         // x: 8 chunks of 1M elems
        src = x   + (size_t)seg * (1024*1024);
        dst = g_x16 + (size_t)seg * (1024*1024);
    } else {
        const int w = seg - 8;
        src = (w == 0) ? Wq : (w == 1) ? Wk : (w == 2) ? Wv : Wo;
        dst = g_W16[w];
    }
    size_t i = ((size_t)blockIdx.x * 256 + threadIdx.x) * 4;
    float4 v = *(const float4*)(src + i);
    uint32_t o[2] = { pack_h16(v.x, v.y), pack_h16(v.z, v.w) };
    *(uint2*)(dst + i) = *(uint2*)o;
}

// ---------------------------------------------------------------------------
// fp16 1-MMA GEMM:  C[m,n] = sum_k A[m,k]*W[n,k] + bias[n]
// 128x128 block, 8 warps, BK=64, 3-stage cp.async (wait_group 1), 2 CTAs/SM.
// mode 0: QKV -> Q (scaled) / K / V plain fp16, scatter [B,H,S,Dh]
// mode 1: O-proj -> fp32 out
// ---------------------------------------------------------------------------
#define BM 128
#define BN 128
#define BK 64
#define NCH (KTOT/BK)          // 16
#define LDK 72
#define TILE_E (128*LDK)       // 9216
#define STAGE_E (2*TILE_E)
#define NSTAGE 3
#define GEMM_SMEM_BYTES (NSTAGE*STAGE_E*2)   // 110592

struct GemmArgs {
    const float* bias0; const float* bias1; const float* bias2;
    float* out_o;
    int mode;
};

__global__ __launch_bounds__(256, 2) void hl_gemm(GemmArgs args)
{
    extern __shared__ __align__(16) char dsm[];
    __half* smT = (__half*)dsm;

    const int t    = threadIdx.x;
    const int wid  = t >> 5;
    const int lane = t & 31;
    const int z    = blockIdx.z;
    const int m0   = blockIdx.y * BM;
    const int n0   = blockIdx.x * BN;
    const int wm   = wid & 1;
    const int wn   = wid >> 1;

    const __half *Ax, *Bx;
    const float* bias;
    if (args.mode == 0) {
        Ax = g_x16;
        Bx = g_W16[z];
        bias = (z == 0) ? args.bias0 : (z == 1) ? args.bias1 : args.bias2;
    } else {
        Ax = g_AO16;
        Bx = g_W16[3];
        bias = args.bias0;
    }
    const __half* srcs[2] = { Ax, Bx };
    const int r0s[2] = { m0, n0 };

    const uint32_t ub = smem_u32(smT);
    const uint32_t abase = (uint32_t)(((wm*64 + (lane & 15)) * LDK + ((lane >> 4) << 3)) * 2);
    const uint32_t bbase = (uint32_t)(((wn*32 + ((lane >> 4) << 3) + (lane & 7)) * LDK
                                      + (((lane >> 3) & 1) << 3)) * 2);

    float c[4][4][4];
#pragma unroll
    for (int mi = 0; mi < 4; mi++)
#pragma unroll
        for (int nj = 0; nj < 4; nj++)
#pragma unroll
            for (int r = 0; r < 4; r++) c[mi][nj][r] = 0.f;

    auto load_stage = [&](int stage, int kc) {
#pragma unroll
        for (int it = 0; it < 8; it++) {
            int idx  = t + it * 256;
            int tile = idx >> 10;
            int rem  = idx & 1023;
            int row  = rem >> 3;
            int ch   = rem & 7;
            const __half* sp = srcs[tile]
                + (size_t)(r0s[tile] + row) * KTOT + kc * BK + ch * 8;
            uint32_t dp = ub + (uint32_t)((stage * 2 + tile) * TILE_E + row * LDK + ch * 8) * 2;
            cp_async16(dp, sp);
        }
        cp_commit();
    };

    load_stage(0, 0);
    load_stage(1, 1);

    for (int kc = 0; kc < NCH; kc++) {
        if (kc + 1 < NCH) cp_wait1(); else cp_wait0();
        __syncthreads();
        if (kc + 2 < NCH) load_stage((kc + 2) % NSTAGE, kc + 2);

        const int s = kc % NSTAGE;
        const uint32_t uA = ub + (uint32_t)((s*2 + 0) * TILE_E) * 2;
        const uint32_t uB = ub + (uint32_t)((s*2 + 1) * TILE_E) * 2;

#pragma unroll
        for (int ks = 0; ks < 4; ks++) {
            uint32_t a[4][4];
#pragma unroll
            for (int mi = 0; mi < 4; mi++)
                ldsm_x4(a[mi], uA + abase + (uint32_t)(mi * 16 * LDK * 2) + ks * 32);
            uint32_t b[2][4];
#pragma unroll
            for (int j2 = 0; j2 < 2; j2++)
                ldsm_x4(b[j2], uB + bbase + (uint32_t)(j2 * 16 * LDK * 2) + ks * 32);
#pragma unroll
            for (int mi = 0; mi < 4; mi++)
#pragma unroll
                for (int nj = 0; nj < 4; nj++)
                    mma_f16(c[mi][nj], a[mi], &b[nj >> 1][(nj & 1) * 2]);
        }
    }

    // -------- register epilogue --------
    const float qscale = (args.mode == 0 && z == 0) ? QSCALE_LOG2E : 1.0f;
    float2 bv[4];
    int nn[4];
#pragma unroll
    for (int nj = 0; nj < 4; nj++) {
        nn[nj] = n0 + wn*32 + nj*8 + (lane & 3)*2;
        bv[nj] = *(const float2*)&bias[nn[nj]];
    }

    if (args.mode == 0) {
        __half* dst = (z == 0) ? g_Q16 : (z == 1) ? g_K16 : g_V16;
#pragma unroll
        for (int mi = 0; mi < 4; mi++) {
#pragma unroll
            for (int half = 0; half < 2; half++) {
                const int m  = m0 + wm*64 + mi*16 + (lane >> 2) + half*8;
                const int bb = m >> 11;
                const int ss = m & (SEQ - 1);
#pragma unroll
                for (int nj = 0; nj < 4; nj++) {
                    const int n  = nn[nj];
                    const int h  = n >> 6;
                    const int dh = n & 63;
                    const float v0 = (c[mi][nj][half*2+0] + bv[nj].x) * qscale;
                    const float v1 = (c[mi][nj][half*2+1] + bv[nj].y) * qscale;
                    const size_t off = (((size_t)bb * NHEADS + h) * SEQ + ss) * HDIM + dh;
                    *(uint32_t*)(dst + off) = pack_h16(v0, v1);
                }
            }
        }
    } else {
        float* outp = args.out_o;
#pragma unroll
        for (int mi = 0; mi < 4; mi++) {
#pragma unroll
            for (int half = 0; half < 2; half++) {
                const int m = m0 + wm*64 + mi*16 + (lane >> 2) + half*8;
#pragma unroll
                for (int nj = 0; nj < 4; nj++) {
                    const float v0 = c[mi][nj][half*2+0] + bv[nj].x;
                    const float v1 = c[mi][nj][half*2+1] + bv[nj].y;
                    *(float2*)(outp + (size_t)m * DMODEL + nn[nj]) = make_float2(v0, v1);
                }
            }
        }
    }
}

// ---------------------------------------------------------------------------
// Register-resident causal flash attention — all plain fp16.
// exp2 via MUFU (ex2.approx), f16x2 packs via single cvt.
// ---------------------------------------------------------------------------
#define ASTR 72
#define KVBUF 18432
#define ATTN_SMEM_BYTES (18432 + 2*KVBUF)   // 55296

__global__ __launch_bounds__(256, 2) void attn_tc()
{
    extern __shared__ __align__(16) char asmem[];
    __half* sQ = (__half*)(asmem);

    const int t    = threadIdx.x;
    const int wid  = t >> 5;
    const int lane = t & 31;
    const int bq   = gridDim.x - 1 - blockIdx.x;   // heavy tiles first
    const int h    = blockIdx.y;
    const int bb   = blockIdx.z;
    const int q0   = bq * 128;
    const size_t base = ((size_t)bb * NHEADS + h) * SEQ * HDIM;

    const char* gsrc[2] = { (const char*)g_K16, (const char*)g_V16 };

    auto load_kv = [&](int buf, int k0) {
        char* dst0 = asmem + 18432 + buf * KVBUF;
#pragma unroll
        for (int it = 0; it < 4; it++) {
            int idx = t + it * 256;
            int a   = idx >> 9;
            int rem = idx & 511;
            int row = rem >> 3, ch = rem & 7;
            uint32_t dp = smem_u32(dst0 + a * 9216 + (row * ASTR + ch * 8) * 2);
            cp_async16(dp, gsrc[a] + (base + (size_t)(k0 + row) * HDIM + ch * 8) * 2);
        }
        cp_commit();
    };

    {
#pragma unroll
        for (int it = 0; it < 4; it++) {
            int idx = t + it * 256;
            int row = idx >> 3, ch = idx & 7;
            uint32_t dp = smem_u32(asmem + (row * ASTR + ch * 8) * 2);
            cp_async16(dp, g_Q16 + base + (size_t)(q0 + row) * HDIM + ch * 8);
        }
        cp_commit();
    }
    load_kv(0, 0);

    const uint32_t uQ = smem_u32(sQ);
    const uint32_t aoff  = (uint32_t)(((wid*16 + (lane & 15)) * ASTR + ((lane >> 4) << 3)) * 2);
    const uint32_t kboff = (uint32_t)(((((lane >> 4) << 3) + (lane & 7)) * ASTR + (((lane >> 3) & 1) << 3)) * 2);
    const uint32_t vboff = (uint32_t)((((((lane >> 3) & 1) << 3) + (lane & 7)) * ASTR + ((lane >> 4) << 3)) * 2);

    float o[8][4];
#pragma unroll
    for (int j = 0; j < 8; j++)
#pragma unroll
        for (int r = 0; r < 4; r++) o[j][r] = 0.f;

    const int rA = q0 + wid*16 + (lane >> 2);
    const int rB = rA + 8;
    const int qwmin = q0 + wid*16;
    const int qwmax = qwmin + 15;
    float mA = -1e30f, mB = -1e30f, lA = 0.f, lB = 0.f;

    const int nkt = 2*bq + 2;
    for (int kt = 0; kt < nkt; kt++) {
        const int k0 = kt * 64;
        cp_wait0();
        __syncthreads();
        if (kt + 1 < nkt) load_kv((kt + 1) & 1, k0 + 64);

        const uint32_t ukv = smem_u32(asmem + 18432 + (kt & 1) * KVBUF);
        const uint32_t uK = ukv, uV = ukv + 9216;

        if (k0 <= qwmax) {
            float c[8][4];
#pragma unroll
            for (int j = 0; j < 8; j++)
#pragma unroll
                for (int r = 0; r < 4; r++) c[j][r] = 0.f;

            // ---- S = Q.K^T ----
#pragma unroll
            for (int ks = 0; ks < 4; ks++) {
                uint32_t a[4];
                ldsm_x4(a, uQ + aoff + ks*32);
#pragma unroll
                for (int jp = 0; jp < 4; jp++) {
                    if (k0 + jp*16 <= qwmax) {
                        uint32_t bk[4];
                        ldsm_x4(bk, uK + kboff + (uint32_t)(jp*16*ASTR*2) + ks*32);
                        mma_f16(c[2*jp],   a, bk);
                        mma_f16(c[2*jp+1], a, bk+2);
                    }
                }
            }

            if (k0 + 63 > qwmin) {
#pragma unroll
                for (int j = 0; j < 8; j++) {
                    int colb = k0 + j*8 + (lane & 3)*2;
                    if (colb     > rA) c[j][0] = -1e30f;
                    if (colb + 1 > rA) c[j][1] = -1e30f;
                    if (colb     > rB) c[j][2] = -1e30f;
                    if (colb + 1 > rB) c[j][3] = -1e30f;
                }
            }

            // ---- online softmax (base-2, MUFU ex2) ----
            float vmA = -1e30f, vmB = -1e30f;
#pragma unroll
            for (int j = 0; j < 8; j++) {
                vmA = fmaxf(vmA, fmaxf(c[j][0], c[j][1]));
                vmB = fmaxf(vmB, fmaxf(c[j][2], c[j][3]));
            }
            vmA = fmaxf(vmA, __shfl_xor_sync(0xffffffffu, vmA, 1));
            vmA = fmaxf(vmA, __shfl_xor_sync(0xffffffffu, vmA, 2));
            vmB = fmaxf(vmB, __shfl_xor_sync(0xffffffffu, vmB, 1));
            vmB = fmaxf(vmB, __shfl_xor_sync(0xffffffffu, vmB, 2));
            const float mnA = fmaxf(mA, vmA);
            const float mnB = fmaxf(mB, vmB);

            float sA = 0.f, sB = 0.f;
#pragma unroll
            for (int j = 0; j < 8; j++) {
                c[j][0] = ex2_fast(c[j][0] - mnA);
                c[j][1] = ex2_fast(c[j][1] - mnA);
                c[j][2] = ex2_fast(c[j][2] - mnB);
                c[j][3] = ex2_fast(c[j][3] - mnB);
                sA += c[j][0] + c[j][1];
                sB += c[j][2] + c[j][3];
            }
            sA += __shfl_xor_sync(0xffffffffu, sA, 1);
            sA += __shfl_xor_sync(0xffffffffu, sA, 2);
            sB += __shfl_xor_sync(0xffffffffu, sB, 1);
            sB += __shfl_xor_sync(0xffffffffu, sB, 2);

            const float soA = ex2_fast(mA - mnA);
            const float soB = ex2_fast(mB - mnB);
            lA = lA * soA + sA;  mA = mnA;
            lB = lB * soB + sB;  mB = mnB;

#pragma unroll
            for (int j = 0; j < 8; j++) {
                o[j][0] *= soA; o[j][1] *= soA;
                o[j][2] *= soB; o[j][3] *= soB;
            }

            // ---- O += P.V ----
#pragma unroll
            for (int kk = 0; kk < 4; kk++) {
                if (k0 + kk*16 <= qwmax) {
                    uint32_t p[4];
                    p[0] = pack_h16(c[2*kk][0],   c[2*kk][1]);
                    p[1] = pack_h16(c[2*kk][2],   c[2*kk][3]);
                    p[2] = pack_h16(c[2*kk+1][0], c[2*kk+1][1]);
                    p[3] = pack_h16(c[2*kk+1][2], c[2*kk+1][3]);
#pragma unroll
                    for (int jp = 0; jp < 4; jp++) {
                        uint32_t v[4];
                        ldsm_x4_t(v, uV + vboff + (uint32_t)(kk*16*ASTR*2) + jp*32);
                        mma_f16(o[2*jp],   p, v);
                        mma_f16(o[2*jp+1], p, v+2);
                    }
                }
            }
        }
    }

    // epilogue: normalize + write plain fp16 AO [b, s, h*64+col]
    {
        const float invA = 1.f / lA;
        const float invB = 1.f / lB;
        const size_t offA = ((size_t)bb * SEQ + rA) * DMODEL + h * HDIM + (lane & 3) * 2;
        const size_t offB = ((size_t)bb * SEQ + rB) * DMODEL + h * HDIM + (lane & 3) * 2;
#pragma unroll
        for (int j = 0; j < 8; j++) {
            *(uint32_t*)(g_AO16 + offA + j*8) = pack_h16(o[j][0] * invA, o[j][1] * invA);
            *(uint32_t*)(g_AO16 + offB + j*8) = pack_h16(o[j][2] * invB, o[j][3] * invB);
        }
    }
}

// ---------------------------------------------------------------------------
extern "C" void kernel_launch(void* const* d_in, const int* in_sizes, int n_in,
                              void* d_out, int out_size)
{
    const float* x  = (const float*)d_in[0];
    const float* Wq = (const float*)d_in[1];
    const float* bq = (const float*)d_in[2];
    const float* Wk = (const float*)d_in[3];
    const float* bk = (const float*)d_in[4];
    const float* Wv = (const float*)d_in[5];
    const float* bv = (const float*)d_in[6];
    const float* Wo = (const float*)d_in[7];
    const float* bo = (const float*)d_in[8];
    float* out = (float*)d_out;

    cudaFuncSetAttribute(hl_gemm, cudaFuncAttributeMaxDynamicSharedMemorySize, GEMM_SMEM_BYTES);
    cudaFuncSetAttribute(attn_tc, cudaFuncAttributeMaxDynamicSharedMemorySize, ATTN_SMEM_BYTES);

    conv_all<<<dim3(1024, 12), 256>>>(x, Wq, Wk, Wv, Wo);

    GemmArgs qa;
    qa.bias0 = bq; qa.bias1 = bk; qa.bias2 = bv; qa.out_o = nullptr; qa.mode = 0;
    hl_gemm<<<dim3(DMODEL/BN, (BATCH*SEQ)/BM, 3), 256, GEMM_SMEM_BYTES>>>(qa);

    attn_tc<<<dim3(SEQ/128, NHEADS, BATCH), 256, ATTN_SMEM_BYTES>>>();

    GemmArgs oa;
    oa.bias0 = bo; oa.bias1 = nullptr; oa.bias2 = nullptr; oa.out_o = out; oa.mode = 1;
    hl_gemm<<<dim3(DMODEL/BN, (BATCH*SEQ)/BM, 1), 256, GEMM_SMEM_BYTES>>>(oa);
}